// round 13
// baseline (speedup 1.0000x reference)
#include <cuda_runtime.h>
#include <math.h>

#define BATCH 4096
#define HID 128
#define NTAN 8
#define MTAN (BATCH * NTAN)
#define DF_ROWS 26624              /* rows on the df64/FFMA chain  (416 tiles) */
#define FP_ROWS (MTAN - DF_ROWS)   /* rows on the fp64/DFMA chain  (96 tiles)  */

typedef unsigned long long u64;

// ---------------- static device scratch (float2 hi/lo, no allocations) ----------------
__device__ float2 dS1[BATCH * HID];
__device__ float2 dS2[BATCH * HID];
__device__ float2 dS3[BATCH * HID];
__device__ float2 dS4[BATCH * HID];
__device__ float2 dH1[BATCH * HID];
__device__ float2 dH2[BATCH * HID];
__device__ float2 dH3[BATCH * HID];
__device__ float2 dG1[BATCH * HID];
__device__ float2 dG2[BATCH * HID];
__device__ float2 dG3[BATCH * HID];
__device__ float2 dQ1[BATCH * HID];
__device__ float2 dQ2[BATCH * HID];
__device__ float2 dQ3[BATCH * HID];
__device__ double dJ[BATCH * 16];
__device__ float2 dTa[MTAN * HID];   // T2
__device__ float2 dTb[MTAN * HID];   // T3 -> later DG1
__device__ float2 dTc[MTAN * HID];   // DG4 -> later DG2
__device__ float2 dTd[MTAN * HID];   // DG3
__device__ double dV[MTAN * 16];

__device__ __forceinline__ double softplus_d(double z) {
    return (z > 40.0) ? z : log1p(exp(z));
}
__device__ __forceinline__ double sigmoid_d(double z) {
    return 1.0 / (1.0 + exp(-z));
}
__device__ __forceinline__ float2 df_make(double v) {
    float h = (float)v;
    return make_float2(h, (float)(v - (double)h));
}
__device__ __forceinline__ double df_dbl(float2 a) { return (double)a.x + (double)a.y; }

// df64 * exact-float -> normalized df64
__device__ __forceinline__ float2 df_mul_f(float2 a, float b) {
    float p = __fmul_rn(a.x, b);
    float e = __fmaf_rn(a.x, b, -p);
    e = __fmaf_rn(a.y, b, e);
    float h = __fadd_rn(p, e);
    float l = __fadd_rn(__fsub_rn(p, h), e);
    return make_float2(h, l);
}
// df64 * df64 -> normalized df64
__device__ __forceinline__ float2 df_mul(float2 a, float2 b) {
    float p = __fmul_rn(a.x, b.x);
    float e = __fmaf_rn(a.x, b.x, -p);
    e = __fmaf_rn(a.x, b.y, e);
    e = __fmaf_rn(a.y, b.x, e);
    float h = __fadd_rn(p, e);
    float l = __fadd_rn(__fsub_rn(p, h), e);
    return make_float2(h, l);
}

// ---------------- packed f32x2 primitives ----------------
__device__ __forceinline__ u64 pk2(float lo, float hi) {
    u64 r;
    asm("mov.b64 %0, {%1, %2};" : "=l"(r) : "f"(lo), "f"(hi));
    return r;
}
__device__ __forceinline__ void upk2(u64 v, float& lo, float& hi) {
    asm("mov.b64 {%0, %1}, %2;" : "=f"(lo), "=f"(hi) : "l"(v));
}
__device__ __forceinline__ u64 mul2(u64 a, u64 b) {
    u64 d; asm("mul.rn.f32x2 %0, %1, %2;" : "=l"(d) : "l"(a), "l"(b)); return d;
}
__device__ __forceinline__ u64 add2(u64 a, u64 b) {
    u64 d; asm("add.rn.f32x2 %0, %1, %2;" : "=l"(d) : "l"(a), "l"(b)); return d;
}
__device__ __forceinline__ u64 fma2(u64 a, u64 b, u64 c) {
    u64 d; asm("fma.rn.f32x2 %0, %1, %2, %3;" : "=l"(d) : "l"(a), "l"(b), "l"(c)); return d;
}
// Packed Kahan + TwoProdFMA: lanes are two independent accumulators.
__device__ __forceinline__ void df_acc2(u64& s, u64& c, u64 ax, u64 ay, u64 b, u64 NEG1) {
    u64 p  = mul2(ax, b);
    u64 np = mul2(p, NEG1);
    u64 e  = fma2(ax, b, np);
    u64 tl = fma2(ay, b, e);
    u64 y  = fma2(c, NEG1, p);    // p - c
    u64 t  = add2(s, y);
    u64 d1 = fma2(s, NEG1, t);    // t - s
    u64 d2 = fma2(y, NEG1, d1);   // d1 - y
    c      = fma2(tl, NEG1, d2);  // d2 - tl
    s = t;
}

// ---------------- layer 1 forward (K=16), fp64 (tiny) ----------------
__global__ void fwd1_kernel(const float* __restrict__ x, const float* __restrict__ W1,
                            const float* __restrict__ b1,
                            float2* __restrict__ H1, float2* __restrict__ S1) {
    int b = blockIdx.x;
    int n = threadIdx.x;  // 0..127
    __shared__ float xs[16];
    if (n < 16) xs[n] = x[b * 16 + n];
    __syncthreads();
    double z = (double)b1[n];
#pragma unroll
    for (int k = 0; k < 16; k++) z = fma((double)xs[k], (double)W1[n * 16 + k], z);
    H1[b * HID + n] = df_make(softplus_d(z));
    S1[b * HID + n] = df_make(sigmoid_d(z));
}

// ---------------- shared epilogue (df64 outputs, fp64 math) ----------------
template <int EPI>
__device__ __forceinline__ void epilogue_store(
    int m, int n, double v,
    const float* bias, const float2* s_epi, const float2* t_epi,
    const float2* q_epi, const float* w_epi,
    float2* out0, float2* out1) {
    int b = m & (BATCH - 1);
    int jdir = m >> 12;
    size_t om = (size_t)m * HID + n;
    if (EPI == 0) {
        double z = v + (double)bias[n];
        out0[om] = df_make(softplus_d(z));
        out1[om] = df_make(sigmoid_d(z));
    } else if (EPI == 1) {
        double s = df_dbl(s_epi[(size_t)b * HID + n]);
        out0[om] = df_make(s * v);                 // G
        out1[om] = df_make(s * (1.0 - s) * v);     // Q = s'(z)*P
    } else if (EPI == 2) {
        out0[om] = df_make(v);
    } else if (EPI == 3) {
        double s = df_dbl(s_epi[(size_t)b * HID + n]);
        out0[om] = df_make(s * (1.0 - s) * v * (double)w_epi[n]);
    } else if (EPI == 4) {
        double q = df_dbl(q_epi[(size_t)b * HID + n]);
        double s = df_dbl(s_epi[(size_t)b * HID + n]);
        double t = df_dbl(t_epi[om]);
        out0[om] = df_make(q * t + s * v);
    } else if (EPI == 5) {
        double q = df_dbl(q_epi[(size_t)b * HID + n]);
        double s = df_dbl(s_epi[(size_t)b * HID + n]);
        double t1n = (double)w_epi[n * 16 + 8 + jdir];
        out0[om] = df_make(q * t1n + s * v);
    } else if (EPI == 6) {
        double z = v + (double)bias[n];
        out1[om] = df_make(sigmoid_d(z));          // S only (H unused)
    }
}

// ---------------- df64 GEMM, packed f32x2 Kahan, 512 thr, 64x64 tile, 2x4 micro ------
// out[m,n] = sum_k a(m,k) * Bmat(k,n), K=128. Global row = m_base + blockIdx.x*64 + r.
// PRO: 0 plain A; 1 A*v0[k]; 2 s_pro[b,k]*A[m,k]; 3 s_pro[b,k]*W1[k,8+j]
// TB : 0 Bmat[k][n]=W[k*128+n]; 1 Bmat[k][n]=W[n*128+k]
template <int PRO, int TB, int EPI>
__global__ __launch_bounds__(512, 2) void gemmT(
    const float2* __restrict__ A, const float* __restrict__ W,
    const float* __restrict__ v0, const float2* __restrict__ s_pro,
    const float* __restrict__ bias, const float2* __restrict__ s_epi,
    const float2* __restrict__ t_epi, const float2* __restrict__ q_epi,
    const float* __restrict__ w_epi,
    float2* __restrict__ out0, float2* __restrict__ out1, int m_base) {
    __shared__ __align__(16) float2 As[2][16][66];
    __shared__ __align__(16) float Bs[2][16][68];

    const int tid = threadIdx.x;
    const int tx = tid & 15;
    const int ty = tid >> 4;
    const int m0 = m_base + blockIdx.x * 64;
    const int n0 = blockIdx.y * 64;

    const int alm = tid >> 3;
    const int alk = (tid & 7) * 2;
    const int gm = m0 + alm;
    const int gb = gm & (BATCH - 1);
    const int gj = gm >> 12;

    const int bk = tid >> 5;
    const int bn = (tid & 31) * 2;
    const int wn = tid >> 3;
    const int wk = (tid & 7) * 2;

    const u64 NEG1 = pk2(-1.f, -1.f);

    float2 a0r, a1r;
    float2 w2r;

#define LOAD_PANEL(k0_)                                                               \
    do {                                                                              \
        if (PRO == 3) {                                                               \
            float4 s4 = *(const float4*)(s_pro + (size_t)gb * HID + (k0_) + alk);     \
            a0r = df_mul_f(make_float2(s4.x, s4.y), v0[((k0_) + alk) * 16 + 8 + gj]); \
            a1r = df_mul_f(make_float2(s4.z, s4.w),                                   \
                           v0[((k0_) + alk + 1) * 16 + 8 + gj]);                      \
        } else {                                                                      \
            float4 av = *(const float4*)(A + (size_t)gm * HID + (k0_) + alk);         \
            a0r = make_float2(av.x, av.y);                                            \
            a1r = make_float2(av.z, av.w);                                            \
            if (PRO == 1) {                                                           \
                a0r = df_mul_f(a0r, v0[(k0_) + alk]);                                 \
                a1r = df_mul_f(a1r, v0[(k0_) + alk + 1]);                             \
            } else if (PRO == 2) {                                                    \
                float4 s4 = *(const float4*)(s_pro + (size_t)gb * HID + (k0_) + alk); \
                a0r = df_mul(a0r, make_float2(s4.x, s4.y));                           \
                a1r = df_mul(a1r, make_float2(s4.z, s4.w));                           \
            }                                                                         \
        }                                                                             \
        if (TB == 0) {                                                                \
            w2r = *(const float2*)(W + ((k0_) + bk) * HID + n0 + bn);                 \
        } else {                                                                      \
            w2r = *(const float2*)(W + (n0 + wn) * HID + (k0_) + wk);                 \
        }                                                                             \
    } while (0)

#define STORE_PANEL(buf_)                                                             \
    do {                                                                              \
        As[buf_][alk][alm] = a0r;                                                     \
        As[buf_][alk + 1][alm] = a1r;                                                 \
        if (TB == 0) {                                                                \
            *(float2*)&Bs[buf_][bk][bn] = w2r;                                        \
        } else {                                                                      \
            Bs[buf_][wk][wn] = w2r.x;                                                 \
            Bs[buf_][wk + 1][wn] = w2r.y;                                             \
        }                                                                             \
    } while (0)

    u64 S00 = pk2(0.f, 0.f), S01 = S00, S10 = S00, S11 = S00;
    u64 C00 = S00, C01 = S00, C10 = S00, C11 = S00;

    LOAD_PANEL(0);
    STORE_PANEL(0);
    __syncthreads();

    for (int p = 0; p < 8; p++) {
        if (p < 7) LOAD_PANEL((p + 1) * 16);
        const int cur = p & 1;
        float4 af = *(const float4*)&As[cur][0][ty * 2];
        float4 bf = *(const float4*)&Bs[cur][0][tx * 4];
#pragma unroll
        for (int kk = 0; kk < 16; kk++) {
            float4 afn, bfn;
            if (kk < 15) {
                afn = *(const float4*)&As[cur][kk + 1][ty * 2];
                bfn = *(const float4*)&Bs[cur][kk + 1][tx * 4];
            }
            u64 b01 = pk2(bf.x, bf.y);
            u64 b23 = pk2(bf.z, bf.w);
            u64 ax0 = pk2(af.x, af.x), ay0 = pk2(af.y, af.y);
            u64 ax1 = pk2(af.z, af.z), ay1 = pk2(af.w, af.w);
            df_acc2(S00, C00, ax0, ay0, b01, NEG1);
            df_acc2(S01, C01, ax0, ay0, b23, NEG1);
            df_acc2(S10, C10, ax1, ay1, b01, NEG1);
            df_acc2(S11, C11, ax1, ay1, b23, NEG1);
            af = afn;
            bf = bfn;
        }
        if (p < 7) STORE_PANEL((p + 1) & 1);
        __syncthreads();
    }
#undef LOAD_PANEL
#undef STORE_PANEL

    float accS[2][4], accC[2][4];
    upk2(S00, accS[0][0], accS[0][1]);
    upk2(S01, accS[0][2], accS[0][3]);
    upk2(S10, accS[1][0], accS[1][1]);
    upk2(S11, accS[1][2], accS[1][3]);
    upk2(C00, accC[0][0], accC[0][1]);
    upk2(C01, accC[0][2], accC[0][3]);
    upk2(C10, accC[1][0], accC[1][1]);
    upk2(C11, accC[1][2], accC[1][3]);

#pragma unroll
    for (int i = 0; i < 2; i++) {
        int m = m0 + ty * 2 + i;
#pragma unroll
        for (int jj = 0; jj < 4; jj++) {
            int n = n0 + tx * 4 + jj;
            double v = (double)accS[i][jj] + (double)accC[i][jj];
            epilogue_store<EPI>(m, n, v, bias, s_epi, t_epi, q_epi, w_epi, out0, out1);
        }
    }
}

// ---------------- fp64 GEMM (DFMA pipe), 256 thr, 64x64 tile, 4x4 micro --------------
// Same semantics as gemmT, fp64 arithmetic, df64 float2 in/out. Double-buffered.
template <int PRO, int TB, int EPI>
__global__ __launch_bounds__(256, 2) void gemmD(
    const float2* __restrict__ A, const float* __restrict__ W,
    const float* __restrict__ v0, const float2* __restrict__ s_pro,
    const float* __restrict__ bias, const float2* __restrict__ s_epi,
    const float2* __restrict__ t_epi, const float2* __restrict__ q_epi,
    const float* __restrict__ w_epi,
    float2* __restrict__ out0, float2* __restrict__ out1, int m_base) {
    __shared__ double As[2][16][65];
    __shared__ double Bs[2][16][65];

    const int tid = threadIdx.x;
    const int tx = tid & 15;   // n sub-block of 4
    const int ty = tid >> 4;   // m sub-block of 4
    const int m0 = m_base + blockIdx.x * 64;
    const int n0 = blockIdx.y * 64;

    const int lm = tid >> 2;          // 0..63
    const int lk = (tid & 3) * 4;     // 0,4,8,12
    const int gm = m0 + lm;
    const int gb = gm & (BATCH - 1);
    const int gj = gm >> 12;

    const int bk = tid >> 4;          // TB==0: k (0..15)
    const int bn = (tid & 15) * 4;    // TB==0: n base
    const int wn = tid >> 2;          // TB==1: n (0..63)
    const int wk = (tid & 3) * 4;     // TB==1: k base

    double areg[4];
    float breg[4];

#define LOAD_PANEL(k0_)                                                              \
    do {                                                                             \
        _Pragma("unroll") for (int u = 0; u < 4; u++) {                              \
            int k = (k0_) + lk + u;                                                  \
            double a;                                                               \
            if (PRO == 3) {                                                          \
                a = df_dbl(s_pro[(size_t)gb * HID + k]) * (double)v0[k * 16 + 8 + gj]; \
            } else {                                                                 \
                a = df_dbl(A[(size_t)gm * HID + k]);                                 \
                if (PRO == 1) a *= (double)v0[k];                                    \
                else if (PRO == 2) a *= df_dbl(s_pro[(size_t)gb * HID + k]);         \
            }                                                                        \
            areg[u] = a;                                                             \
        }                                                                            \
        if (TB == 0) {                                                               \
            float4 w4 = *(const float4*)(W + ((k0_) + bk) * HID + n0 + bn);          \
            breg[0] = w4.x; breg[1] = w4.y; breg[2] = w4.z; breg[3] = w4.w;          \
        } else {                                                                     \
            float4 w4 = *(const float4*)(W + (n0 + wn) * HID + (k0_) + wk);          \
            breg[0] = w4.x; breg[1] = w4.y; breg[2] = w4.z; breg[3] = w4.w;          \
        }                                                                            \
    } while (0)

#define STORE_PANEL(buf_)                                                            \
    do {                                                                             \
        _Pragma("unroll") for (int u = 0; u < 4; u++) As[buf_][lk + u][lm] = areg[u];\
        if (TB == 0) {                                                               \
            _Pragma("unroll") for (int u = 0; u < 4; u++)                            \
                Bs[buf_][bk][bn + u] = (double)breg[u];                              \
        } else {                                                                     \
            _Pragma("unroll") for (int u = 0; u < 4; u++)                            \
                Bs[buf_][wk + u][wn] = (double)breg[u];                              \
        }                                                                            \
    } while (0)

    double acc[4][4];
#pragma unroll
    for (int i = 0; i < 4; i++)
#pragma unroll
        for (int j = 0; j < 4; j++) acc[i][j] = 0.0;

    LOAD_PANEL(0);
    STORE_PANEL(0);
    __syncthreads();

    for (int p = 0; p < 8; p++) {
        if (p < 7) LOAD_PANEL((p + 1) * 16);
        const int cur = p & 1;
#pragma unroll
        for (int kk = 0; kk < 16; kk++) {
            double a[4], b[4];
#pragma unroll
            for (int i = 0; i < 4; i++) a[i] = As[cur][kk][ty * 4 + i];
#pragma unroll
            for (int j = 0; j < 4; j++) b[j] = Bs[cur][kk][tx * 4 + j];
#pragma unroll
            for (int i = 0; i < 4; i++)
#pragma unroll
                for (int j = 0; j < 4; j++) acc[i][j] = fma(a[i], b[j], acc[i][j]);
        }
        if (p < 7) STORE_PANEL((p + 1) & 1);
        __syncthreads();
    }
#undef LOAD_PANEL
#undef STORE_PANEL

#pragma unroll
    for (int i = 0; i < 4; i++) {
        int m = m0 + ty * 4 + i;
#pragma unroll
        for (int jj = 0; jj < 4; jj++) {
            int n = n0 + tx * 4 + jj;
            epilogue_store<EPI>(m, n, acc[i][jj], bias, s_epi, t_epi, q_epi, w_epi, out0, out1);
        }
    }
}

// ---------------- packed projection onto W1 (N=16): out[m,c] = sum_n In[m,n]*W1[n,c] --
__global__ void proj16_kernel(const float2* __restrict__ In, const float* __restrict__ W1,
                              double* __restrict__ out, int m_base) {
    __shared__ u64 w2s[HID][9];
    __shared__ u64 rx[16][HID + 1];
    __shared__ u64 ry[16][HID + 1];
    const int tid = threadIdx.x;
    const u64 NEG1 = pk2(-1.f, -1.f);

    for (int i = tid; i < HID * 8; i += 128) {
        int n = i >> 3, cp = i & 7;
        w2s[n][cp] = pk2(W1[n * 16 + 2 * cp], W1[n * 16 + 2 * cp + 1]);
    }
    {
        int lr = tid >> 3;
        int c0 = (tid & 7) * 16;
        size_t m = (size_t)m_base + blockIdx.x * 16 + lr;
#pragma unroll
        for (int u = 0; u < 16; u++) {
            float2 v = In[m * HID + c0 + u];
            rx[lr][c0 + u] = pk2(v.x, v.x);
            ry[lr][c0 + u] = pk2(v.y, v.y);
        }
    }
    __syncthreads();

    const int lr = tid >> 3;
    const int cp = tid & 7;
    size_t m = (size_t)m_base + blockIdx.x * 16 + lr;
    u64 Sa = pk2(0.f, 0.f), Ca = Sa;
#pragma unroll 8
    for (int n = 0; n < HID; n++) {
        u64 ax = rx[lr][n], ay = ry[lr][n], b = w2s[n][cp];
        u64 p = mul2(ax, b);
        u64 np = mul2(p, NEG1);
        u64 e = fma2(ax, b, np);
        u64 tl = fma2(ay, b, e);
        u64 y = fma2(Ca, NEG1, p);
        u64 t = add2(Sa, y);
        u64 d1 = fma2(Sa, NEG1, t);
        u64 d2 = fma2(y, NEG1, d1);
        Ca = fma2(tl, NEG1, d2);
        Sa = t;
    }
    float s0, s1, c0f, c1f;
    upk2(Sa, s0, s1);
    upk2(Ca, c0f, c1f);
    out[m * 16 + 2 * cp]     = (double)s0 + (double)c0f;
    out[m * 16 + 2 * cp + 1] = (double)s1 + (double)c1f;
}

// ---------------- per-sample 8x8 symmetric pinv solve (Jacobi, fp64, 7 sweeps) -------
__global__ void solve_kernel(const double* __restrict__ V, const double* __restrict__ J,
                             const float* __restrict__ x, float* __restrict__ out) {
    int b = blockIdx.x * blockDim.x + threadIdx.x;
    if (b >= BATCH) return;
    double A[8][8], Vec[8][8], rhs[8];
    for (int r = 0; r < 8; r++) {
        for (int c = 0; c < 8; c++) {
            double v1 = V[((size_t)c * BATCH + b) * 16 + 8 + r];
            double v2 = V[((size_t)r * BATCH + b) * 16 + 8 + c];
            A[r][c] = 0.5 * (v1 + v2);
            Vec[r][c] = (r == c) ? 1.0 : 0.0;
        }
        double s = J[(size_t)b * 16 + r];
        for (int c = 0; c < 8; c++)
            s -= V[((size_t)r * BATCH + b) * 16 + c] * (double)x[b * 16 + 8 + c];
        rhs[r] = s;
    }
    for (int sweep = 0; sweep < 7; sweep++) {
        for (int p = 0; p < 7; p++) {
            for (int q = p + 1; q < 8; q++) {
                double apq = A[p][q];
                if (fabs(apq) < 1e-300) continue;
                double theta = (A[q][q] - A[p][p]) / (2.0 * apq);
                double t = ((theta >= 0.0) ? 1.0 : -1.0) / (fabs(theta) + sqrt(theta * theta + 1.0));
                double c = 1.0 / sqrt(t * t + 1.0);
                double s = t * c;
                for (int k = 0; k < 8; k++) {
                    double t1 = A[p][k], t2 = A[q][k];
                    A[p][k] = c * t1 - s * t2;
                    A[q][k] = s * t1 + c * t2;
                }
                for (int k = 0; k < 8; k++) {
                    double t1 = A[k][p], t2 = A[k][q];
                    A[k][p] = c * t1 - s * t2;
                    A[k][q] = s * t1 + c * t2;
                }
                for (int k = 0; k < 8; k++) {
                    double t1 = Vec[k][p], t2 = Vec[k][q];
                    Vec[k][p] = c * t1 - s * t2;
                    Vec[k][q] = s * t1 + c * t2;
                }
            }
        }
    }
    double amax = 0.0;
    for (int k = 0; k < 8; k++) amax = fmax(amax, fabs(A[k][k]));
    double cutoff = 9.5367431640625e-06 * amax;  // jnp pinv f32 cutoff
    double y[8];
    for (int r = 0; r < 8; r++) y[r] = 0.0;
    for (int k = 0; k < 8; k++) {
        double lam = A[k][k];
        if (fabs(lam) <= cutoff) continue;
        double dot = 0.0;
        for (int r = 0; r < 8; r++) dot += Vec[r][k] * rhs[r];
        double w = dot / lam;
        for (int r = 0; r < 8; r++) y[r] += w * Vec[r][k];
    }
    for (int r = 0; r < 8; r++) out[b * 8 + r] = (float)y[r];
}

// ---------------- host ----------------
extern "C" void kernel_launch(void* const* d_in, const int* in_sizes, int n_in,
                              void* d_out, int out_size) {
    const float* x  = (const float*)d_in[0];
    const float* W1 = (const float*)d_in[1];
    const float* b1 = (const float*)d_in[2];
    const float* W2 = (const float*)d_in[3];
    const float* b2 = (const float*)d_in[4];
    const float* W3 = (const float*)d_in[5];
    const float* b3 = (const float*)d_in[6];
    const float* W4 = (const float*)d_in[7];
    const float* b4 = (const float*)d_in[8];
    const float* W5 = (const float*)d_in[9];
    float* out = (float*)d_out;

    float2 *pS1, *pS2, *pS3, *pS4, *pH1, *pH2, *pH3;
    float2 *pG1, *pG2, *pG3, *pQ1, *pQ2, *pQ3;
    float2 *pTa, *pTb, *pTc, *pTd;
    double *pJ, *pV;
    cudaGetSymbolAddress((void**)&pS1, dS1);
    cudaGetSymbolAddress((void**)&pS2, dS2);
    cudaGetSymbolAddress((void**)&pS3, dS3);
    cudaGetSymbolAddress((void**)&pS4, dS4);
    cudaGetSymbolAddress((void**)&pH1, dH1);
    cudaGetSymbolAddress((void**)&pH2, dH2);
    cudaGetSymbolAddress((void**)&pH3, dH3);
    cudaGetSymbolAddress((void**)&pG1, dG1);
    cudaGetSymbolAddress((void**)&pG2, dG2);
    cudaGetSymbolAddress((void**)&pG3, dG3);
    cudaGetSymbolAddress((void**)&pQ1, dQ1);
    cudaGetSymbolAddress((void**)&pQ2, dQ2);
    cudaGetSymbolAddress((void**)&pQ3, dQ3);
    cudaGetSymbolAddress((void**)&pJ, dJ);
    cudaGetSymbolAddress((void**)&pTa, dTa);
    cudaGetSymbolAddress((void**)&pTb, dTb);
    cudaGetSymbolAddress((void**)&pTc, dTc);
    cudaGetSymbolAddress((void**)&pTd, dTd);
    cudaGetSymbolAddress((void**)&pV, dV);

    // one-time side streams + events (created on first, uncaptured, call)
    static cudaStream_t s1 = nullptr, s2 = nullptr;
    static cudaEvent_t evS1, evS2, evS4, evG3, evG2, evG1, evJ, evA, evD;
    if (s1 == nullptr) {
        cudaStreamCreateWithFlags(&s1, cudaStreamNonBlocking);
        cudaStreamCreateWithFlags(&s2, cudaStreamNonBlocking);
        cudaEventCreateWithFlags(&evS1, cudaEventDisableTiming);
        cudaEventCreateWithFlags(&evS2, cudaEventDisableTiming);
        cudaEventCreateWithFlags(&evS4, cudaEventDisableTiming);
        cudaEventCreateWithFlags(&evG3, cudaEventDisableTiming);
        cudaEventCreateWithFlags(&evG2, cudaEventDisableTiming);
        cudaEventCreateWithFlags(&evG1, cudaEventDisableTiming);
        cudaEventCreateWithFlags(&evJ, cudaEventDisableTiming);
        cudaEventCreateWithFlags(&evA, cudaEventDisableTiming);
        cudaEventCreateWithFlags(&evD, cudaEventDisableTiming);
    }

    const dim3 GB(BATCH / 64, 2);      // base passes: 128 blocks
    const dim3 GF(DF_ROWS / 64, 2);    // df64 tangent part: 832 blocks
    const dim3 GD(FP_ROWS / 64, 2);    // fp64 tangent part: 192 blocks
    cudaStream_t s0 = 0;               // harness/capture stream

    // ---- stream 0: fwd1 (produces S1, H1) ----
    fwd1_kernel<<<BATCH, 128, 0, s0>>>(x, W1, b1, pH1, pS1);
    cudaEventRecord(evS1, s0);

    // ---- T2 on both tangent chains (needs only S1) ----
    cudaStreamWaitEvent(s1, evS1, 0);
    gemmT<3, 1, 2><<<GF, 512, 0, s1>>>(nullptr, W2, W1, pS1, nullptr, nullptr, nullptr, nullptr, nullptr, pTa, nullptr, 0);
    cudaStreamWaitEvent(s2, evS1, 0);
    gemmD<3, 1, 2><<<GD, 256, 0, s2>>>(nullptr, W2, W1, pS1, nullptr, nullptr, nullptr, nullptr, nullptr, pTa, nullptr, DF_ROWS);

    // ---- stream 0: base forward chain ----
    gemmT<0, 1, 0><<<GB, 512, 0, s0>>>(pH1, W2, nullptr, nullptr, b2, nullptr, nullptr, nullptr, nullptr, pH2, pS2, 0);
    cudaEventRecord(evS2, s0);
    gemmT<0, 1, 0><<<GB, 512, 0, s0>>>(pH2, W3, nullptr, nullptr, b3, nullptr, nullptr, nullptr, nullptr, pH3, pS3, 0);
    gemmT<0, 1, 6><<<GB, 512, 0, s0>>>(pH3, W4, nullptr, nullptr, b4, nullptr, nullptr, nullptr, nullptr, nullptr, pS4, 0);
    cudaEventRecord(evS4, s0);

    // ---- stream 0: backward chain + J ----
    gemmT<1, 0, 1><<<GB, 512, 0, s0>>>(pS4, W4, W5, nullptr, nullptr, pS3, nullptr, nullptr, nullptr, pG3, pQ3, 0);
    cudaEventRecord(evG3, s0);
    gemmT<0, 0, 1><<<GB, 512, 0, s0>>>(pG3, W3, nullptr, nullptr, nullptr, pS2, nullptr, nullptr, nullptr, pG2, pQ2, 0);
    cudaEventRecord(evG2, s0);
    gemmT<0, 0, 1><<<GB, 512, 0, s0>>>(pG2, W2, nullptr, nullptr, nullptr, pS1, nullptr, nullptr, nullptr, pG1, pQ1, 0);
    cudaEventRecord(evG1, s0);
    proj16_kernel<<<BATCH / 16, 128, 0, s0>>>(pG1, W1, pJ, 0);
    cudaEventRecord(evJ, s0);

    // ---- df64 tangent chain, rows [0, DF_ROWS) on s1 ----
    cudaStreamWaitEvent(s1, evS2, 0);
    gemmT<2, 1, 2><<<GF, 512, 0, s1>>>(pTa, W3, nullptr, pS2, nullptr, nullptr, nullptr, nullptr, nullptr, pTb, nullptr, 0);
    cudaStreamWaitEvent(s1, evS4, 0);
    gemmT<2, 1, 3><<<GF, 512, 0, s1>>>(pTb, W4, nullptr, pS3, nullptr, pS4, nullptr, nullptr, W5, pTc, nullptr, 0);
    cudaStreamWaitEvent(s1, evG3, 0);
    gemmT<0, 0, 4><<<GF, 512, 0, s1>>>(pTc, W4, nullptr, nullptr, nullptr, pS3, pTb, pQ3, nullptr, pTd, nullptr, 0);
    cudaStreamWaitEvent(s1, evG2, 0);
    gemmT<0, 0, 4><<<GF, 512, 0, s1>>>(pTd, W3, nullptr, nullptr, nullptr, pS2, pTa, pQ2, nullptr, pTc, nullptr, 0);
    cudaStreamWaitEvent(s1, evG1, 0);
    gemmT<0, 0, 5><<<GF, 512, 0, s1>>>(pTc, W2, nullptr, nullptr, nullptr, pS1, nullptr, pQ1, W1, pTb, nullptr, 0);

    // ---- fp64 tangent chain, rows [DF_ROWS, MTAN) on s2 ----
    cudaStreamWaitEvent(s2, evS2, 0);
    gemmD<2, 1, 2><<<GD, 256, 0, s2>>>(pTa, W3, nullptr, pS2, nullptr, nullptr, nullptr, nullptr, nullptr, pTb, nullptr, DF_ROWS);
    cudaStreamWaitEvent(s2, evS4, 0);
    gemmD<2, 1, 3><<<GD, 256, 0, s2>>>(pTb, W4, nullptr, pS3, nullptr, pS4, nullptr, nullptr, W5, pTc, nullptr, DF_ROWS);
    cudaStreamWaitEvent(s2, evG3, 0);
    gemmD<0, 0, 4><<<GD, 256, 0, s2>>>(pTc, W4, nullptr, nullptr, nullptr, pS3, pTb, pQ3, nullptr, pTd, nullptr, DF_ROWS);
    cudaStreamWaitEvent(s2, evG2, 0);
    gemmD<0, 0, 4><<<GD, 256, 0, s2>>>(pTd, W3, nullptr, nullptr, nullptr, pS2, pTa, pQ2, nullptr, pTc, nullptr, DF_ROWS);
    cudaStreamWaitEvent(s2, evG1, 0);
    gemmD<0, 0, 5><<<GD, 256, 0, s2>>>(pTc, W2, nullptr, nullptr, nullptr, pS1, nullptr, pQ1, W1, pTb, nullptr, DF_ROWS);
    cudaEventRecord(evD, s2);

    // ---- projection over ALL tangent rows + solve, after both chains + J ----
    cudaStreamWaitEvent(s1, evD, 0);
    proj16_kernel<<<MTAN / 16, 128, 0, s1>>>(pTb, W1, pV, 0);
    cudaStreamWaitEvent(s1, evJ, 0);
    solve_kernel<<<BATCH / 32, 32, 0, s1>>>(pV, pJ, x, out);
    cudaEventRecord(evA, s1);

    // ---- join back onto the capture stream ----
    cudaStreamWaitEvent(s0, evA, 0);
}

// round 14
// speedup vs baseline: 1.4000x; 1.4000x over previous
#include <cuda_runtime.h>
#include <math.h>

#define BATCH 4096
#define HID 128
#define NTAN 8
#define MTAN (BATCH * NTAN)
#define MHALF (MTAN / 2)

typedef unsigned long long u64;

// ---------------- static device scratch (float2 hi/lo, no allocations) ----------------
__device__ float2 dS1[BATCH * HID];
__device__ float2 dS2[BATCH * HID];
__device__ float2 dS3[BATCH * HID];
__device__ float2 dS4[BATCH * HID];
__device__ float2 dH1[BATCH * HID];
__device__ float2 dH2[BATCH * HID];
__device__ float2 dH3[BATCH * HID];
__device__ float2 dG1[BATCH * HID];
__device__ float2 dG2[BATCH * HID];
__device__ float2 dG3[BATCH * HID];
__device__ float2 dQ1[BATCH * HID];
__device__ float2 dQ2[BATCH * HID];
__device__ float2 dQ3[BATCH * HID];
__device__ double dJ[BATCH * 16];
__device__ float2 dTa[MTAN * HID];   // T2
__device__ float2 dTb[MTAN * HID];   // T3 -> later DG1
__device__ float2 dTc[MTAN * HID];   // DG4 -> later DG2
__device__ float2 dTd[MTAN * HID];   // DG3
__device__ double dV[MTAN * 16];

__device__ __forceinline__ double softplus_d(double z) {
    return (z > 40.0) ? z : log1p(exp(z));
}
__device__ __forceinline__ double sigmoid_d(double z) {
    return 1.0 / (1.0 + exp(-z));
}
__device__ __forceinline__ float2 df_make(double v) {
    float h = (float)v;
    return make_float2(h, (float)(v - (double)h));
}
__device__ __forceinline__ double df_dbl(float2 a) { return (double)a.x + (double)a.y; }

// df64 * exact-float -> normalized df64
__device__ __forceinline__ float2 df_mul_f(float2 a, float b) {
    float p = __fmul_rn(a.x, b);
    float e = __fmaf_rn(a.x, b, -p);
    e = __fmaf_rn(a.y, b, e);
    float h = __fadd_rn(p, e);
    float l = __fadd_rn(__fsub_rn(p, h), e);
    return make_float2(h, l);
}
// df64 * df64 -> normalized df64
__device__ __forceinline__ float2 df_mul(float2 a, float2 b) {
    float p = __fmul_rn(a.x, b.x);
    float e = __fmaf_rn(a.x, b.x, -p);
    e = __fmaf_rn(a.x, b.y, e);
    e = __fmaf_rn(a.y, b.x, e);
    float h = __fadd_rn(p, e);
    float l = __fadd_rn(__fsub_rn(p, h), e);
    return make_float2(h, l);
}

// ---------------- packed f32x2 primitives ----------------
__device__ __forceinline__ u64 pk2(float lo, float hi) {
    u64 r;
    asm("mov.b64 %0, {%1, %2};" : "=l"(r) : "f"(lo), "f"(hi));
    return r;
}
__device__ __forceinline__ void upk2(u64 v, float& lo, float& hi) {
    asm("mov.b64 {%0, %1}, %2;" : "=f"(lo), "=f"(hi) : "l"(v));
}
__device__ __forceinline__ u64 mul2(u64 a, u64 b) {
    u64 d; asm("mul.rn.f32x2 %0, %1, %2;" : "=l"(d) : "l"(a), "l"(b)); return d;
}
__device__ __forceinline__ u64 add2(u64 a, u64 b) {
    u64 d; asm("add.rn.f32x2 %0, %1, %2;" : "=l"(d) : "l"(a), "l"(b)); return d;
}
__device__ __forceinline__ u64 fma2(u64 a, u64 b, u64 c) {
    u64 d; asm("fma.rn.f32x2 %0, %1, %2, %3;" : "=l"(d) : "l"(a), "l"(b), "l"(c)); return d;
}
// Packed Kahan + TwoProdFMA: lanes are two independent accumulators.
__device__ __forceinline__ void df_acc2(u64& s, u64& c, u64 ax, u64 ay, u64 b, u64 NEG1) {
    u64 p  = mul2(ax, b);
    u64 np = mul2(p, NEG1);
    u64 e  = fma2(ax, b, np);
    u64 tl = fma2(ay, b, e);
    u64 y  = fma2(c, NEG1, p);    // p - c
    u64 t  = add2(s, y);
    u64 d1 = fma2(s, NEG1, t);    // t - s
    u64 d2 = fma2(y, NEG1, d1);   // d1 - y
    c      = fma2(tl, NEG1, d2);  // d2 - tl
    s = t;
}

// ---------------- layer 1 forward (K=16), fp64 (tiny) ----------------
__global__ void fwd1_kernel(const float* __restrict__ x, const float* __restrict__ W1,
                            const float* __restrict__ b1,
                            float2* __restrict__ H1, float2* __restrict__ S1) {
    int b = blockIdx.x;
    int n = threadIdx.x;  // 0..127
    __shared__ float xs[16];
    if (n < 16) xs[n] = x[b * 16 + n];
    __syncthreads();
    double z = (double)b1[n];
#pragma unroll
    for (int k = 0; k < 16; k++) z = fma((double)xs[k], (double)W1[n * 16 + k], z);
    H1[b * HID + n] = df_make(softplus_d(z));
    S1[b * HID + n] = df_make(sigmoid_d(z));
}

// ---------------- df64 GEMM, packed f32x2 Kahan, 512 thr, 64x64 tile, 2x4 micro ------
// out[m,n] = sum_k a(m,k) * Bmat(k,n), K=128.  Global row = m_base + blockIdx.x*64 + r.
// PRO: 0 plain A; 1 A*v0[k]; 2 s_pro[b,k]*A[m,k]; 3 s_pro[b,k]*W1[k,8+j]
// TB : 0 Bmat[k][n]=W[k*128+n]; 1 Bmat[k][n]=W[n*128+k]
// EPI: 0 act (H,S); 1 G,Q; 2 store acc; 3 DG4; 4 DG mid; 5 DG1; 6 S only
template <int PRO, int TB, int EPI>
__global__ __launch_bounds__(512, 2) void gemmT(
    const float2* __restrict__ A, const float* __restrict__ W,
    const float* __restrict__ v0, const float2* __restrict__ s_pro,
    const float* __restrict__ bias, const float2* __restrict__ s_epi,
    const float2* __restrict__ t_epi, const float2* __restrict__ q_epi,
    const float* __restrict__ w_epi,
    float2* __restrict__ out0, float2* __restrict__ out1, int m_base) {
    __shared__ __align__(16) float2 As[2][16][66];
    __shared__ __align__(16) float Bs[2][16][68];

    const int tid = threadIdx.x;
    const int tx = tid & 15;   // n sub-block of 4
    const int ty = tid >> 4;   // m sub-block of 2 (0..31)
    const int m0 = m_base + blockIdx.x * 64;
    const int n0 = blockIdx.y * 64;

    const int alm = tid >> 3;          // 0..63
    const int alk = (tid & 7) * 2;     // 0,2,..,14
    const int gm = m0 + alm;
    const int gb = gm & (BATCH - 1);
    const int gj = gm >> 12;

    const int bk = tid >> 5;           // TB==0: k index (0..15)
    const int bn = (tid & 31) * 2;     // TB==0: n pair base
    const int wn = tid >> 3;           // TB==1: n index (0..63)
    const int wk = (tid & 7) * 2;      // TB==1: k pair base

    const u64 NEG1 = pk2(-1.f, -1.f);

    float2 a0r, a1r;
    float2 w2r;

#define LOAD_PANEL(k0_)                                                               \
    do {                                                                              \
        if (PRO == 3) {                                                               \
            float4 s4 = *(const float4*)(s_pro + (size_t)gb * HID + (k0_) + alk);     \
            a0r = df_mul_f(make_float2(s4.x, s4.y), v0[((k0_) + alk) * 16 + 8 + gj]); \
            a1r = df_mul_f(make_float2(s4.z, s4.w),                                   \
                           v0[((k0_) + alk + 1) * 16 + 8 + gj]);                      \
        } else {                                                                      \
            float4 av = *(const float4*)(A + (size_t)gm * HID + (k0_) + alk);         \
            a0r = make_float2(av.x, av.y);                                            \
            a1r = make_float2(av.z, av.w);                                            \
            if (PRO == 1) {                                                           \
                a0r = df_mul_f(a0r, v0[(k0_) + alk]);                                 \
                a1r = df_mul_f(a1r, v0[(k0_) + alk + 1]);                             \
            } else if (PRO == 2) {                                                    \
                float4 s4 = *(const float4*)(s_pro + (size_t)gb * HID + (k0_) + alk); \
                a0r = df_mul(a0r, make_float2(s4.x, s4.y));                           \
                a1r = df_mul(a1r, make_float2(s4.z, s4.w));                           \
            }                                                                         \
        }                                                                             \
        if (TB == 0) {                                                                \
            w2r = *(const float2*)(W + ((k0_) + bk) * HID + n0 + bn);                 \
        } else {                                                                      \
            w2r = *(const float2*)(W + (n0 + wn) * HID + (k0_) + wk);                 \
        }                                                                             \
    } while (0)

#define STORE_PANEL(buf_)                                                             \
    do {                                                                              \
        As[buf_][alk][alm] = a0r;                                                     \
        As[buf_][alk + 1][alm] = a1r;                                                 \
        if (TB == 0) {                                                                \
            *(float2*)&Bs[buf_][bk][bn] = w2r;                                        \
        } else {                                                                      \
            Bs[buf_][wk][wn] = w2r.x;                                                 \
            Bs[buf_][wk + 1][wn] = w2r.y;                                             \
        }                                                                             \
    } while (0)

    // packed accumulators: [i][jpair], lanes = (j, j+1)
    u64 S00 = pk2(0.f, 0.f), S01 = S00, S10 = S00, S11 = S00;
    u64 C00 = S00, C01 = S00, C10 = S00, C11 = S00;

    LOAD_PANEL(0);
    STORE_PANEL(0);
    __syncthreads();

    for (int p = 0; p < 8; p++) {
        if (p < 7) LOAD_PANEL((p + 1) * 16);  // gmem loads overlap compute
        const int cur = p & 1;
        float4 af = *(const float4*)&As[cur][0][ty * 2];
        float4 bf = *(const float4*)&Bs[cur][0][tx * 4];
#pragma unroll
        for (int kk = 0; kk < 16; kk++) {
            float4 afn, bfn;
            if (kk < 15) {
                afn = *(const float4*)&As[cur][kk + 1][ty * 2];
                bfn = *(const float4*)&Bs[cur][kk + 1][tx * 4];
            }
            u64 b01 = pk2(bf.x, bf.y);
            u64 b23 = pk2(bf.z, bf.w);
            u64 ax0 = pk2(af.x, af.x), ay0 = pk2(af.y, af.y);
            u64 ax1 = pk2(af.z, af.z), ay1 = pk2(af.w, af.w);
            df_acc2(S00, C00, ax0, ay0, b01, NEG1);
            df_acc2(S01, C01, ax0, ay0, b23, NEG1);
            df_acc2(S10, C10, ax1, ay1, b01, NEG1);
            df_acc2(S11, C11, ax1, ay1, b23, NEG1);
            af = afn;
            bf = bfn;
        }
        if (p < 7) STORE_PANEL((p + 1) & 1);
        __syncthreads();
    }
#undef LOAD_PANEL
#undef STORE_PANEL

    float accS[2][4], accC[2][4];
    upk2(S00, accS[0][0], accS[0][1]);
    upk2(S01, accS[0][2], accS[0][3]);
    upk2(S10, accS[1][0], accS[1][1]);
    upk2(S11, accS[1][2], accS[1][3]);
    upk2(C00, accC[0][0], accC[0][1]);
    upk2(C01, accC[0][2], accC[0][3]);
    upk2(C10, accC[1][0], accC[1][1]);
    upk2(C11, accC[1][2], accC[1][3]);

#pragma unroll
    for (int i = 0; i < 2; i++) {
        int m = m0 + ty * 2 + i;
        int b = m & (BATCH - 1);
        int jdir = m >> 12;
#pragma unroll
        for (int jj = 0; jj < 4; jj++) {
            int n = n0 + tx * 4 + jj;
            double v = (double)accS[i][jj] + (double)accC[i][jj];
            size_t om = (size_t)m * HID + n;
            if (EPI == 0) {
                double z = v + (double)bias[n];
                out0[om] = df_make(softplus_d(z));
                out1[om] = df_make(sigmoid_d(z));
            } else if (EPI == 1) {
                double s = df_dbl(s_epi[(size_t)b * HID + n]);
                out0[om] = df_make(s * v);                 // G
                out1[om] = df_make(s * (1.0 - s) * v);     // Q = s'(z)*P
            } else if (EPI == 2) {
                out0[om] = df_make(v);
            } else if (EPI == 3) {
                double s = df_dbl(s_epi[(size_t)b * HID + n]);
                out0[om] = df_make(s * (1.0 - s) * v * (double)w_epi[n]);
            } else if (EPI == 4) {
                double q = df_dbl(q_epi[(size_t)b * HID + n]);
                double s = df_dbl(s_epi[(size_t)b * HID + n]);
                double t = df_dbl(t_epi[om]);
                out0[om] = df_make(q * t + s * v);
            } else if (EPI == 5) {
                double q = df_dbl(q_epi[(size_t)b * HID + n]);
                double s = df_dbl(s_epi[(size_t)b * HID + n]);
                double t1n = (double)w_epi[n * 16 + 8 + jdir];
                out0[om] = df_make(q * t1n + s * v);
            } else if (EPI == 6) {
                double z = v + (double)bias[n];
                out1[om] = df_make(sigmoid_d(z));          // S only (H unused)
            }
        }
    }
}

// ---------------- packed projection onto W1 (N=16): out[m,c] = sum_n In[m,n]*W1[n,c] --
__global__ void proj16_kernel(const float2* __restrict__ In, const float* __restrict__ W1,
                              double* __restrict__ out, int m_base) {
    __shared__ u64 w2s[HID][9];      // [n][cpair], padded
    __shared__ u64 rx[16][HID + 1];
    __shared__ u64 ry[16][HID + 1];
    const int tid = threadIdx.x;
    const u64 NEG1 = pk2(-1.f, -1.f);

    for (int i = tid; i < HID * 8; i += 128) {
        int n = i >> 3, cp = i & 7;
        w2s[n][cp] = pk2(W1[n * 16 + 2 * cp], W1[n * 16 + 2 * cp + 1]);
    }
    {
        int lr = tid >> 3;
        int c0 = (tid & 7) * 16;
        size_t m = (size_t)m_base + blockIdx.x * 16 + lr;
#pragma unroll
        for (int u = 0; u < 16; u++) {
            float2 v = In[m * HID + c0 + u];
            rx[lr][c0 + u] = pk2(v.x, v.x);
            ry[lr][c0 + u] = pk2(v.y, v.y);
        }
    }
    __syncthreads();

    const int lr = tid >> 3;
    const int cp = tid & 7;
    size_t m = (size_t)m_base + blockIdx.x * 16 + lr;
    u64 Sa = pk2(0.f, 0.f), Ca = Sa;
#pragma unroll 8
    for (int n = 0; n < HID; n++) {
        u64 ax = rx[lr][n], ay = ry[lr][n], b = w2s[n][cp];
        u64 p = mul2(ax, b);
        u64 np = mul2(p, NEG1);
        u64 e = fma2(ax, b, np);
        u64 tl = fma2(ay, b, e);
        u64 y = fma2(Ca, NEG1, p);
        u64 t = add2(Sa, y);
        u64 d1 = fma2(Sa, NEG1, t);
        u64 d2 = fma2(y, NEG1, d1);
        Ca = fma2(tl, NEG1, d2);
        Sa = t;
    }
    float s0, s1, c0f, c1f;
    upk2(Sa, s0, s1);
    upk2(Ca, c0f, c1f);
    out[m * 16 + 2 * cp]     = (double)s0 + (double)c0f;
    out[m * 16 + 2 * cp + 1] = (double)s1 + (double)c1f;
}

// ---------------- per-sample 8x8 symmetric pinv solve (Jacobi, fp64, 7 sweeps) -------
__global__ void solve_kernel(const double* __restrict__ V, const double* __restrict__ J,
                             const float* __restrict__ x, float* __restrict__ out) {
    int b = blockIdx.x * blockDim.x + threadIdx.x;
    if (b >= BATCH) return;
    double A[8][8], Vec[8][8], rhs[8];
    for (int r = 0; r < 8; r++) {
        for (int c = 0; c < 8; c++) {
            double v1 = V[((size_t)c * BATCH + b) * 16 + 8 + r];
            double v2 = V[((size_t)r * BATCH + b) * 16 + 8 + c];
            A[r][c] = 0.5 * (v1 + v2);
            Vec[r][c] = (r == c) ? 1.0 : 0.0;
        }
        double s = J[(size_t)b * 16 + r];
        for (int c = 0; c < 8; c++)
            s -= V[((size_t)r * BATCH + b) * 16 + c] * (double)x[b * 16 + 8 + c];
        rhs[r] = s;
    }
    for (int sweep = 0; sweep < 7; sweep++) {
        for (int p = 0; p < 7; p++) {
            for (int q = p + 1; q < 8; q++) {
                double apq = A[p][q];
                if (fabs(apq) < 1e-300) continue;
                double theta = (A[q][q] - A[p][p]) / (2.0 * apq);
                double t = ((theta >= 0.0) ? 1.0 : -1.0) / (fabs(theta) + sqrt(theta * theta + 1.0));
                double c = 1.0 / sqrt(t * t + 1.0);
                double s = t * c;
                for (int k = 0; k < 8; k++) {
                    double t1 = A[p][k], t2 = A[q][k];
                    A[p][k] = c * t1 - s * t2;
                    A[q][k] = s * t1 + c * t2;
                }
                for (int k = 0; k < 8; k++) {
                    double t1 = A[k][p], t2 = A[k][q];
                    A[k][p] = c * t1 - s * t2;
                    A[k][q] = s * t1 + c * t2;
                }
                for (int k = 0; k < 8; k++) {
                    double t1 = Vec[k][p], t2 = Vec[k][q];
                    Vec[k][p] = c * t1 - s * t2;
                    Vec[k][q] = s * t1 + c * t2;
                }
            }
        }
    }
    double amax = 0.0;
    for (int k = 0; k < 8; k++) amax = fmax(amax, fabs(A[k][k]));
    double cutoff = 9.5367431640625e-06 * amax;  // jnp pinv f32 cutoff
    double y[8];
    for (int r = 0; r < 8; r++) y[r] = 0.0;
    for (int k = 0; k < 8; k++) {
        double lam = A[k][k];
        if (fabs(lam) <= cutoff) continue;
        double dot = 0.0;
        for (int r = 0; r < 8; r++) dot += Vec[r][k] * rhs[r];
        double w = dot / lam;
        for (int r = 0; r < 8; r++) y[r] += w * Vec[r][k];
    }
    for (int r = 0; r < 8; r++) out[b * 8 + r] = (float)y[r];
}

// ---------------- host ----------------
extern "C" void kernel_launch(void* const* d_in, const int* in_sizes, int n_in,
                              void* d_out, int out_size) {
    const float* x  = (const float*)d_in[0];
    const float* W1 = (const float*)d_in[1];
    const float* b1 = (const float*)d_in[2];
    const float* W2 = (const float*)d_in[3];
    const float* b2 = (const float*)d_in[4];
    const float* W3 = (const float*)d_in[5];
    const float* b3 = (const float*)d_in[6];
    const float* W4 = (const float*)d_in[7];
    const float* b4 = (const float*)d_in[8];
    const float* W5 = (const float*)d_in[9];
    float* out = (float*)d_out;

    float2 *pS1, *pS2, *pS3, *pS4, *pH1, *pH2, *pH3;
    float2 *pG1, *pG2, *pG3, *pQ1, *pQ2, *pQ3;
    float2 *pTa, *pTb, *pTc, *pTd;
    double *pJ, *pV;
    cudaGetSymbolAddress((void**)&pS1, dS1);
    cudaGetSymbolAddress((void**)&pS2, dS2);
    cudaGetSymbolAddress((void**)&pS3, dS3);
    cudaGetSymbolAddress((void**)&pS4, dS4);
    cudaGetSymbolAddress((void**)&pH1, dH1);
    cudaGetSymbolAddress((void**)&pH2, dH2);
    cudaGetSymbolAddress((void**)&pH3, dH3);
    cudaGetSymbolAddress((void**)&pG1, dG1);
    cudaGetSymbolAddress((void**)&pG2, dG2);
    cudaGetSymbolAddress((void**)&pG3, dG3);
    cudaGetSymbolAddress((void**)&pQ1, dQ1);
    cudaGetSymbolAddress((void**)&pQ2, dQ2);
    cudaGetSymbolAddress((void**)&pQ3, dQ3);
    cudaGetSymbolAddress((void**)&pJ, dJ);
    cudaGetSymbolAddress((void**)&pTa, dTa);
    cudaGetSymbolAddress((void**)&pTb, dTb);
    cudaGetSymbolAddress((void**)&pTc, dTc);
    cudaGetSymbolAddress((void**)&pTd, dTd);
    cudaGetSymbolAddress((void**)&pV, dV);

    // one-time side streams + events (created on first, uncaptured, call)
    static cudaStream_t s1 = nullptr, s2 = nullptr;
    static cudaEvent_t evS1, evS2, evS4, evG3, evG2, evG1, evJ, evA, evB;
    if (s1 == nullptr) {
        cudaStreamCreateWithFlags(&s1, cudaStreamNonBlocking);
        cudaStreamCreateWithFlags(&s2, cudaStreamNonBlocking);
        cudaEventCreateWithFlags(&evS1, cudaEventDisableTiming);
        cudaEventCreateWithFlags(&evS2, cudaEventDisableTiming);
        cudaEventCreateWithFlags(&evS4, cudaEventDisableTiming);
        cudaEventCreateWithFlags(&evG3, cudaEventDisableTiming);
        cudaEventCreateWithFlags(&evG2, cudaEventDisableTiming);
        cudaEventCreateWithFlags(&evG1, cudaEventDisableTiming);
        cudaEventCreateWithFlags(&evJ, cudaEventDisableTiming);
        cudaEventCreateWithFlags(&evA, cudaEventDisableTiming);
        cudaEventCreateWithFlags(&evB, cudaEventDisableTiming);
    }

    const dim3 GB(BATCH / 64, 2);    // base passes: 128 blocks
    const dim3 GH(MHALF / 64, 2);    // half-tangent passes: 512 blocks
    cudaStream_t s0 = 0;             // harness/capture stream

    // ---- stream 0: fwd1 (produces S1, H1) ----
    fwd1_kernel<<<BATCH, 128, 0, s0>>>(x, W1, b1, pH1, pS1);
    cudaEventRecord(evS1, s0);

    // ---- tangent halves: T2 = W2 (S1 * t1) — needs only S1 ----
    cudaStreamWaitEvent(s1, evS1, 0);
    gemmT<3, 1, 2><<<GH, 512, 0, s1>>>(nullptr, W2, W1, pS1, nullptr, nullptr, nullptr, nullptr, nullptr, pTa, nullptr, 0);
    cudaStreamWaitEvent(s2, evS1, 0);
    gemmT<3, 1, 2><<<GH, 512, 0, s2>>>(nullptr, W2, W1, pS1, nullptr, nullptr, nullptr, nullptr, nullptr, pTa, nullptr, MHALF);

    // ---- stream 0: base forward chain ----
    gemmT<0, 1, 0><<<GB, 512, 0, s0>>>(pH1, W2, nullptr, nullptr, b2, nullptr, nullptr, nullptr, nullptr, pH2, pS2, 0);
    cudaEventRecord(evS2, s0);
    gemmT<0, 1, 0><<<GB, 512, 0, s0>>>(pH2, W3, nullptr, nullptr, b3, nullptr, nullptr, nullptr, nullptr, pH3, pS3, 0);
    gemmT<0, 1, 6><<<GB, 512, 0, s0>>>(pH3, W4, nullptr, nullptr, b4, nullptr, nullptr, nullptr, nullptr, nullptr, pS4, 0);
    cudaEventRecord(evS4, s0);

    // ---- stream 0: backward chain + J (concurrent with tangent chains) ----
    gemmT<1, 0, 1><<<GB, 512, 0, s0>>>(pS4, W4, W5, nullptr, nullptr, pS3, nullptr, nullptr, nullptr, pG3, pQ3, 0);
    cudaEventRecord(evG3, s0);
    gemmT<0, 0, 1><<<GB, 512, 0, s0>>>(pG3, W3, nullptr, nullptr, nullptr, pS2, nullptr, nullptr, nullptr, pG2, pQ2, 0);
    cudaEventRecord(evG2, s0);
    gemmT<0, 0, 1><<<GB, 512, 0, s0>>>(pG2, W2, nullptr, nullptr, nullptr, pS1, nullptr, nullptr, nullptr, pG1, pQ1, 0);
    cudaEventRecord(evG1, s0);
    proj16_kernel<<<BATCH / 16, 128, 0, s0>>>(pG1, W1, pJ, 0);
    cudaEventRecord(evJ, s0);

    // ---- tangent chain, half A (dirs 0-3) on s1 ----
    cudaStreamWaitEvent(s1, evS2, 0);
    gemmT<2, 1, 2><<<GH, 512, 0, s1>>>(pTa, W3, nullptr, pS2, nullptr, nullptr, nullptr, nullptr, nullptr, pTb, nullptr, 0);
    cudaStreamWaitEvent(s1, evS4, 0);
    gemmT<2, 1, 3><<<GH, 512, 0, s1>>>(pTb, W4, nullptr, pS3, nullptr, pS4, nullptr, nullptr, W5, pTc, nullptr, 0);
    cudaStreamWaitEvent(s1, evG3, 0);
    gemmT<0, 0, 4><<<GH, 512, 0, s1>>>(pTc, W4, nullptr, nullptr, nullptr, pS3, pTb, pQ3, nullptr, pTd, nullptr, 0);
    cudaStreamWaitEvent(s1, evG2, 0);
    gemmT<0, 0, 4><<<GH, 512, 0, s1>>>(pTd, W3, nullptr, nullptr, nullptr, pS2, pTa, pQ2, nullptr, pTc, nullptr, 0);
    cudaStreamWaitEvent(s1, evG1, 0);
    gemmT<0, 0, 5><<<GH, 512, 0, s1>>>(pTc, W2, nullptr, nullptr, nullptr, pS1, nullptr, pQ1, W1, pTb, nullptr, 0);
    proj16_kernel<<<MHALF / 16, 128, 0, s1>>>(pTb, W1, pV, 0);

    // ---- tangent chain, half B (dirs 4-7) on s2 ----
    cudaStreamWaitEvent(s2, evS2, 0);
    gemmT<2, 1, 2><<<GH, 512, 0, s2>>>(pTa, W3, nullptr, pS2, nullptr, nullptr, nullptr, nullptr, nullptr, pTb, nullptr, MHALF);
    cudaStreamWaitEvent(s2, evS4, 0);
    gemmT<2, 1, 3><<<GH, 512, 0, s2>>>(pTb, W4, nullptr, pS3, nullptr, pS4, nullptr, nullptr, W5, pTc, nullptr, MHALF);
    cudaStreamWaitEvent(s2, evG3, 0);
    gemmT<0, 0, 4><<<GH, 512, 0, s2>>>(pTc, W4, nullptr, nullptr, nullptr, pS3, pTb, pQ3, nullptr, pTd, nullptr, MHALF);
    cudaStreamWaitEvent(s2, evG2, 0);
    gemmT<0, 0, 4><<<GH, 512, 0, s2>>>(pTd, W3, nullptr, nullptr, nullptr, pS2, pTa, pQ2, nullptr, pTc, nullptr, MHALF);
    cudaStreamWaitEvent(s2, evG1, 0);
    gemmT<0, 0, 5><<<GH, 512, 0, s2>>>(pTc, W2, nullptr, nullptr, nullptr, pS1, nullptr, pQ1, W1, pTb, nullptr, MHALF);
    proj16_kernel<<<MHALF / 16, 128, 0, s2>>>(pTb, W1, pV, MHALF);
    cudaEventRecord(evB, s2);

    // ---- solve on s1 after both halves + J ----
    cudaStreamWaitEvent(s1, evB, 0);
    cudaStreamWaitEvent(s1, evJ, 0);
    solve_kernel<<<BATCH / 32, 32, 0, s1>>>(pV, pJ, x, out);
    cudaEventRecord(evA, s1);

    // ---- join back onto the capture stream ----
    cudaStreamWaitEvent(s0, evA, 0);
}

// round 15
// speedup vs baseline: 1.4027x; 1.0019x over previous
#include <cuda_runtime.h>
#include <math.h>

#define BATCH 4096
#define HID 128
#define NTAN 8
#define MTAN (BATCH * NTAN)
#define MHALF (MTAN / 2)

typedef unsigned long long u64;

// ---------------- static device scratch (float2 hi/lo, no allocations) ----------------
__device__ float2 dS1[BATCH * HID];
__device__ float2 dS2[BATCH * HID];
__device__ float2 dS3[BATCH * HID];
__device__ float2 dS4[BATCH * HID];
__device__ float2 dH1[BATCH * HID];
__device__ float2 dH2[BATCH * HID];
__device__ float2 dH3[BATCH * HID];
__device__ float2 dG1[BATCH * HID];
__device__ float2 dG2[BATCH * HID];
__device__ float2 dG3[BATCH * HID];
__device__ float2 dQ1[BATCH * HID];
__device__ float2 dQ2[BATCH * HID];
__device__ float2 dQ3[BATCH * HID];
__device__ double dJ[BATCH * 16];
__device__ float2 dTa[MTAN * HID];   // T2
__device__ float2 dTb[MTAN * HID];   // T3 -> later DG1
__device__ float2 dTc[MTAN * HID];   // DG4 -> later DG2
__device__ float2 dTd[MTAN * HID];   // DG3
__device__ double dV[MTAN * 16];

__device__ __forceinline__ double softplus_d(double z) {
    return (z > 40.0) ? z : log1p(exp(z));
}
__device__ __forceinline__ double sigmoid_d(double z) {
    return 1.0 / (1.0 + exp(-z));
}
__device__ __forceinline__ float2 df_make(double v) {
    float h = (float)v;
    return make_float2(h, (float)(v - (double)h));
}
__device__ __forceinline__ double df_dbl(float2 a) { return (double)a.x + (double)a.y; }

// df64 * exact-float -> normalized df64
__device__ __forceinline__ float2 df_mul_f(float2 a, float b) {
    float p = __fmul_rn(a.x, b);
    float e = __fmaf_rn(a.x, b, -p);
    e = __fmaf_rn(a.y, b, e);
    float h = __fadd_rn(p, e);
    float l = __fadd_rn(__fsub_rn(p, h), e);
    return make_float2(h, l);
}
// df64 * df64 -> normalized df64
__device__ __forceinline__ float2 df_mul(float2 a, float2 b) {
    float p = __fmul_rn(a.x, b.x);
    float e = __fmaf_rn(a.x, b.x, -p);
    e = __fmaf_rn(a.x, b.y, e);
    e = __fmaf_rn(a.y, b.x, e);
    float h = __fadd_rn(p, e);
    float l = __fadd_rn(__fsub_rn(p, h), e);
    return make_float2(h, l);
}

// ---------------- packed f32x2 primitives ----------------
__device__ __forceinline__ u64 pk2(float lo, float hi) {
    u64 r;
    asm("mov.b64 %0, {%1, %2};" : "=l"(r) : "f"(lo), "f"(hi));
    return r;
}
__device__ __forceinline__ void upk2(u64 v, float& lo, float& hi) {
    asm("mov.b64 {%0, %1}, %2;" : "=f"(lo), "=f"(hi) : "l"(v));
}
__device__ __forceinline__ u64 mul2(u64 a, u64 b) {
    u64 d; asm("mul.rn.f32x2 %0, %1, %2;" : "=l"(d) : "l"(a), "l"(b)); return d;
}
__device__ __forceinline__ u64 add2(u64 a, u64 b) {
    u64 d; asm("add.rn.f32x2 %0, %1, %2;" : "=l"(d) : "l"(a), "l"(b)); return d;
}
__device__ __forceinline__ u64 sub2(u64 a, u64 b) {
    u64 d; asm("sub.rn.f32x2 %0, %1, %2;" : "=l"(d) : "l"(a), "l"(b)); return d;
}
__device__ __forceinline__ u64 fma2(u64 a, u64 b, u64 c) {
    u64 d; asm("fma.rn.f32x2 %0, %1, %2, %3;" : "=l"(d) : "l"(a), "l"(b), "l"(c)); return d;
}
// Packed Kahan + TwoProdFMA: lanes are two independent accumulators.
// Subtractions use native sub.rn.f32x2 (2-source: lower RF-bank pressure);
// rounding per lane identical to fma(x,-1,y) (both correctly-rounded y-x).
__device__ __forceinline__ void df_acc2(u64& s, u64& c, u64 ax, u64 ay, u64 b, u64 NEG1) {
    u64 p  = mul2(ax, b);
    u64 np = mul2(p, NEG1);
    u64 e  = fma2(ax, b, np);
    u64 tl = fma2(ay, b, e);
    u64 y  = sub2(p, c);      // p - c
    u64 t  = add2(s, y);
    u64 d1 = sub2(t, s);      // t - s
    u64 d2 = sub2(d1, y);     // d1 - y
    c      = sub2(d2, tl);    // d2 - tl
    s = t;
}

// ---------------- layer 1 forward (K=16), fp64 (tiny) ----------------
__global__ void fwd1_kernel(const float* __restrict__ x, const float* __restrict__ W1,
                            const float* __restrict__ b1,
                            float2* __restrict__ H1, float2* __restrict__ S1) {
    int b = blockIdx.x;
    int n = threadIdx.x;  // 0..127
    __shared__ float xs[16];
    if (n < 16) xs[n] = x[b * 16 + n];
    __syncthreads();
    double z = (double)b1[n];
#pragma unroll
    for (int k = 0; k < 16; k++) z = fma((double)xs[k], (double)W1[n * 16 + k], z);
    H1[b * HID + n] = df_make(softplus_d(z));
    S1[b * HID + n] = df_make(sigmoid_d(z));
}

// ---------------- df64 GEMM, packed f32x2 Kahan, 512 thr, 64x64 tile, 2x4 micro ------
// out[m,n] = sum_k a(m,k) * Bmat(k,n), K=128.  Global row = m_base + blockIdx.x*64 + r.
// PRO: 0 plain A; 1 A*v0[k]; 2 s_pro[b,k]*A[m,k]; 3 s_pro[b,k]*W1[k,8+j]
// TB : 0 Bmat[k][n]=W[k*128+n]; 1 Bmat[k][n]=W[n*128+k]
// EPI: 0 act (H,S); 1 G,Q; 2 store acc; 3 DG4; 4 DG mid; 5 DG1; 6 S only
template <int PRO, int TB, int EPI>
__global__ __launch_bounds__(512, 2) void gemmT(
    const float2* __restrict__ A, const float* __restrict__ W,
    const float* __restrict__ v0, const float2* __restrict__ s_pro,
    const float* __restrict__ bias, const float2* __restrict__ s_epi,
    const float2* __restrict__ t_epi, const float2* __restrict__ q_epi,
    const float* __restrict__ w_epi,
    float2* __restrict__ out0, float2* __restrict__ out1, int m_base) {
    __shared__ __align__(16) float2 As[2][16][66];
    __shared__ __align__(16) float Bs[2][16][68];

    const int tid = threadIdx.x;
    const int tx = tid & 15;   // n sub-block of 4
    const int ty = tid >> 4;   // m sub-block of 2 (0..31)
    const int m0 = m_base + blockIdx.x * 64;
    const int n0 = blockIdx.y * 64;

    const int alm = tid >> 3;          // 0..63
    const int alk = (tid & 7) * 2;     // 0,2,..,14
    const int gm = m0 + alm;
    const int gb = gm & (BATCH - 1);
    const int gj = gm >> 12;

    const int bk = tid >> 5;           // TB==0: k index (0..15)
    const int bn = (tid & 31) * 2;     // TB==0: n pair base
    const int wn = tid >> 3;           // TB==1: n index (0..63)
    const int wk = (tid & 7) * 2;      // TB==1: k pair base

    const u64 NEG1 = pk2(-1.f, -1.f);

    float2 a0r, a1r;
    float2 w2r;

#define LOAD_PANEL(k0_)                                                               \
    do {                                                                              \
        if (PRO == 3) {                                                               \
            float4 s4 = *(const float4*)(s_pro + (size_t)gb * HID + (k0_) + alk);     \
            a0r = df_mul_f(make_float2(s4.x, s4.y), v0[((k0_) + alk) * 16 + 8 + gj]); \
            a1r = df_mul_f(make_float2(s4.z, s4.w),                                   \
                           v0[((k0_) + alk + 1) * 16 + 8 + gj]);                      \
        } else {                                                                      \
            float4 av = *(const float4*)(A + (size_t)gm * HID + (k0_) + alk);         \
            a0r = make_float2(av.x, av.y);                                            \
            a1r = make_float2(av.z, av.w);                                            \
            if (PRO == 1) {                                                           \
                a0r = df_mul_f(a0r, v0[(k0_) + alk]);                                 \
                a1r = df_mul_f(a1r, v0[(k0_) + alk + 1]);                             \
            } else if (PRO == 2) {                                                    \
                float4 s4 = *(const float4*)(s_pro + (size_t)gb * HID + (k0_) + alk); \
                a0r = df_mul(a0r, make_float2(s4.x, s4.y));                           \
                a1r = df_mul(a1r, make_float2(s4.z, s4.w));                           \
            }                                                                         \
        }                                                                             \
        if (TB == 0) {                                                                \
            w2r = *(const float2*)(W + ((k0_) + bk) * HID + n0 + bn);                 \
        } else {                                                                      \
            w2r = *(const float2*)(W + (n0 + wn) * HID + (k0_) + wk);                 \
        }                                                                             \
    } while (0)

#define STORE_PANEL(buf_)                                                             \
    do {                                                                              \
        As[buf_][alk][alm] = a0r;                                                     \
        As[buf_][alk + 1][alm] = a1r;                                                 \
        if (TB == 0) {                                                                \
            *(float2*)&Bs[buf_][bk][bn] = w2r;                                        \
        } else {                                                                      \
            Bs[buf_][wk][wn] = w2r.x;                                                 \
            Bs[buf_][wk + 1][wn] = w2r.y;                                             \
        }                                                                             \
    } while (0)

    // packed accumulators: [i][jpair], lanes = (j, j+1)
    u64 S00 = pk2(0.f, 0.f), S01 = S00, S10 = S00, S11 = S00;
    u64 C00 = S00, C01 = S00, C10 = S00, C11 = S00;

    LOAD_PANEL(0);
    STORE_PANEL(0);
    __syncthreads();

    for (int p = 0; p < 8; p++) {
        if (p < 7) LOAD_PANEL((p + 1) * 16);  // gmem loads overlap compute
        const int cur = p & 1;
        float4 af = *(const float4*)&As[cur][0][ty * 2];
        float4 bf = *(const float4*)&Bs[cur][0][tx * 4];
#pragma unroll
        for (int kk = 0; kk < 16; kk++) {
            float4 afn, bfn;
            if (kk < 15) {
                afn = *(const float4*)&As[cur][kk + 1][ty * 2];
                bfn = *(const float4*)&Bs[cur][kk + 1][tx * 4];
            }
            u64 b01 = pk2(bf.x, bf.y);
            u64 b23 = pk2(bf.z, bf.w);
            u64 ax0 = pk2(af.x, af.x), ay0 = pk2(af.y, af.y);
            u64 ax1 = pk2(af.z, af.z), ay1 = pk2(af.w, af.w);
            df_acc2(S00, C00, ax0, ay0, b01, NEG1);
            df_acc2(S01, C01, ax0, ay0, b23, NEG1);
            df_acc2(S10, C10, ax1, ay1, b01, NEG1);
            df_acc2(S11, C11, ax1, ay1, b23, NEG1);
            af = afn;
            bf = bfn;
        }
        if (p < 7) STORE_PANEL((p + 1) & 1);
        __syncthreads();
    }
#undef LOAD_PANEL
#undef STORE_PANEL

    float accS[2][4], accC[2][4];
    upk2(S00, accS[0][0], accS[0][1]);
    upk2(S01, accS[0][2], accS[0][3]);
    upk2(S10, accS[1][0], accS[1][1]);
    upk2(S11, accS[1][2], accS[1][3]);
    upk2(C00, accC[0][0], accC[0][1]);
    upk2(C01, accC[0][2], accC[0][3]);
    upk2(C10, accC[1][0], accC[1][1]);
    upk2(C11, accC[1][2], accC[1][3]);

#pragma unroll
    for (int i = 0; i < 2; i++) {
        int m = m0 + ty * 2 + i;
        int b = m & (BATCH - 1);
        int jdir = m >> 12;
#pragma unroll
        for (int jj = 0; jj < 4; jj++) {
            int n = n0 + tx * 4 + jj;
            double v = (double)accS[i][jj] + (double)accC[i][jj];
            size_t om = (size_t)m * HID + n;
            if (EPI == 0) {
                double z = v + (double)bias[n];
                out0[om] = df_make(softplus_d(z));
                out1[om] = df_make(sigmoid_d(z));
            } else if (EPI == 1) {
                double s = df_dbl(s_epi[(size_t)b * HID + n]);
                out0[om] = df_make(s * v);                 // G
                out1[om] = df_make(s * (1.0 - s) * v);     // Q = s'(z)*P
            } else if (EPI == 2) {
                out0[om] = df_make(v);
            } else if (EPI == 3) {
                double s = df_dbl(s_epi[(size_t)b * HID + n]);
                out0[om] = df_make(s * (1.0 - s) * v * (double)w_epi[n]);
            } else if (EPI == 4) {
                double q = df_dbl(q_epi[(size_t)b * HID + n]);
                double s = df_dbl(s_epi[(size_t)b * HID + n]);
                double t = df_dbl(t_epi[om]);
                out0[om] = df_make(q * t + s * v);
            } else if (EPI == 5) {
                double q = df_dbl(q_epi[(size_t)b * HID + n]);
                double s = df_dbl(s_epi[(size_t)b * HID + n]);
                double t1n = (double)w_epi[n * 16 + 8 + jdir];
                out0[om] = df_make(q * t1n + s * v);
            } else if (EPI == 6) {
                double z = v + (double)bias[n];
                out1[om] = df_make(sigmoid_d(z));          // S only (H unused)
            }
        }
    }
}

// ---------------- packed projection onto W1 (N=16): out[m,c] = sum_n In[m,n]*W1[n,c] --
__global__ void proj16_kernel(const float2* __restrict__ In, const float* __restrict__ W1,
                              double* __restrict__ out, int m_base) {
    __shared__ u64 w2s[HID][9];      // [n][cpair], padded
    __shared__ u64 rx[16][HID + 1];
    __shared__ u64 ry[16][HID + 1];
    const int tid = threadIdx.x;
    const u64 NEG1 = pk2(-1.f, -1.f);

    for (int i = tid; i < HID * 8; i += 128) {
        int n = i >> 3, cp = i & 7;
        w2s[n][cp] = pk2(W1[n * 16 + 2 * cp], W1[n * 16 + 2 * cp + 1]);
    }
    {
        int lr = tid >> 3;
        int c0 = (tid & 7) * 16;
        size_t m = (size_t)m_base + blockIdx.x * 16 + lr;
#pragma unroll
        for (int u = 0; u < 16; u++) {
            float2 v = In[m * HID + c0 + u];
            rx[lr][c0 + u] = pk2(v.x, v.x);
            ry[lr][c0 + u] = pk2(v.y, v.y);
        }
    }
    __syncthreads();

    const int lr = tid >> 3;
    const int cp = tid & 7;
    size_t m = (size_t)m_base + blockIdx.x * 16 + lr;
    u64 Sa = pk2(0.f, 0.f), Ca = Sa;
#pragma unroll 8
    for (int n = 0; n < HID; n++) {
        u64 ax = rx[lr][n], ay = ry[lr][n], b = w2s[n][cp];
        u64 p = mul2(ax, b);
        u64 np = mul2(p, NEG1);
        u64 e = fma2(ax, b, np);
        u64 tl = fma2(ay, b, e);
        u64 y = sub2(p, Ca);
        u64 t = add2(Sa, y);
        u64 d1 = sub2(t, Sa);
        u64 d2 = sub2(d1, y);
        Ca = sub2(d2, tl);
        Sa = t;
    }
    float s0, s1, c0f, c1f;
    upk2(Sa, s0, s1);
    upk2(Ca, c0f, c1f);
    out[m * 16 + 2 * cp]     = (double)s0 + (double)c0f;
    out[m * 16 + 2 * cp + 1] = (double)s1 + (double)c1f;
}

// ---------------- per-sample 8x8 symmetric pinv solve (Jacobi, fp64, 7 sweeps) -------
__global__ void solve_kernel(const double* __restrict__ V, const double* __restrict__ J,
                             const float* __restrict__ x, float* __restrict__ out) {
    int b = blockIdx.x * blockDim.x + threadIdx.x;
    if (b >= BATCH) return;
    double A[8][8], Vec[8][8], rhs[8];
    for (int r = 0; r < 8; r++) {
        for (int c = 0; c < 8; c++) {
            double v1 = V[((size_t)c * BATCH + b) * 16 + 8 + r];
            double v2 = V[((size_t)r * BATCH + b) * 16 + 8 + c];
            A[r][c] = 0.5 * (v1 + v2);
            Vec[r][c] = (r == c) ? 1.0 : 0.0;
        }
        double s = J[(size_t)b * 16 + r];
        for (int c = 0; c < 8; c++)
            s -= V[((size_t)r * BATCH + b) * 16 + c] * (double)x[b * 16 + 8 + c];
        rhs[r] = s;
    }
    for (int sweep = 0; sweep < 7; sweep++) {
        for (int p = 0; p < 7; p++) {
            for (int q = p + 1; q < 8; q++) {
                double apq = A[p][q];
                if (fabs(apq) < 1e-300) continue;
                double theta = (A[q][q] - A[p][p]) / (2.0 * apq);
                double t = ((theta >= 0.0) ? 1.0 : -1.0) / (fabs(theta) + sqrt(theta * theta + 1.0));
                double c = 1.0 / sqrt(t * t + 1.0);
                double s = t * c;
                for (int k = 0; k < 8; k++) {
                    double t1 = A[p][k], t2 = A[q][k];
                    A[p][k] = c * t1 - s * t2;
                    A[q][k] = s * t1 + c * t2;
                }
                for (int k = 0; k < 8; k++) {
                    double t1 = A[k][p], t2 = A[k][q];
                    A[k][p] = c * t1 - s * t2;
                    A[k][q] = s * t1 + c * t2;
                }
                for (int k = 0; k < 8; k++) {
                    double t1 = Vec[k][p], t2 = Vec[k][q];
                    Vec[k][p] = c * t1 - s * t2;
                    Vec[k][q] = s * t1 + c * t2;
                }
            }
        }
    }
    double amax = 0.0;
    for (int k = 0; k < 8; k++) amax = fmax(amax, fabs(A[k][k]));
    double cutoff = 9.5367431640625e-06 * amax;  // jnp pinv f32 cutoff
    double y[8];
    for (int r = 0; r < 8; r++) y[r] = 0.0;
    for (int k = 0; k < 8; k++) {
        double lam = A[k][k];
        if (fabs(lam) <= cutoff) continue;
        double dot = 0.0;
        for (int r = 0; r < 8; r++) dot += Vec[r][k] * rhs[r];
        double w = dot / lam;
        for (int r = 0; r < 8; r++) y[r] += w * Vec[r][k];
    }
    for (int r = 0; r < 8; r++) out[b * 8 + r] = (float)y[r];
}

// ---------------- host ----------------
extern "C" void kernel_launch(void* const* d_in, const int* in_sizes, int n_in,
                              void* d_out, int out_size) {
    const float* x  = (const float*)d_in[0];
    const float* W1 = (const float*)d_in[1];
    const float* b1 = (const float*)d_in[2];
    const float* W2 = (const float*)d_in[3];
    const float* b2 = (const float*)d_in[4];
    const float* W3 = (const float*)d_in[5];
    const float* b3 = (const float*)d_in[6];
    const float* W4 = (const float*)d_in[7];
    const float* b4 = (const float*)d_in[8];
    const float* W5 = (const float*)d_in[9];
    float* out = (float*)d_out;

    float2 *pS1, *pS2, *pS3, *pS4, *pH1, *pH2, *pH3;
    float2 *pG1, *pG2, *pG3, *pQ1, *pQ2, *pQ3;
    float2 *pTa, *pTb, *pTc, *pTd;
    double *pJ, *pV;
    cudaGetSymbolAddress((void**)&pS1, dS1);
    cudaGetSymbolAddress((void**)&pS2, dS2);
    cudaGetSymbolAddress((void**)&pS3, dS3);
    cudaGetSymbolAddress((void**)&pS4, dS4);
    cudaGetSymbolAddress((void**)&pH1, dH1);
    cudaGetSymbolAddress((void**)&pH2, dH2);
    cudaGetSymbolAddress((void**)&pH3, dH3);
    cudaGetSymbolAddress((void**)&pG1, dG1);
    cudaGetSymbolAddress((void**)&pG2, dG2);
    cudaGetSymbolAddress((void**)&pG3, dG3);
    cudaGetSymbolAddress((void**)&pQ1, dQ1);
    cudaGetSymbolAddress((void**)&pQ2, dQ2);
    cudaGetSymbolAddress((void**)&pQ3, dQ3);
    cudaGetSymbolAddress((void**)&pJ, dJ);
    cudaGetSymbolAddress((void**)&pTa, dTa);
    cudaGetSymbolAddress((void**)&pTb, dTb);
    cudaGetSymbolAddress((void**)&pTc, dTc);
    cudaGetSymbolAddress((void**)&pTd, dTd);
    cudaGetSymbolAddress((void**)&pV, dV);

    // one-time side streams + events (created on first, uncaptured, call)
    static cudaStream_t s1 = nullptr, s2 = nullptr;
    static cudaEvent_t evS1, evS2, evS4, evG3, evG2, evG1, evJ, evA, evB;
    if (s1 == nullptr) {
        cudaStreamCreateWithFlags(&s1, cudaStreamNonBlocking);
        cudaStreamCreateWithFlags(&s2, cudaStreamNonBlocking);
        cudaEventCreateWithFlags(&evS1, cudaEventDisableTiming);
        cudaEventCreateWithFlags(&evS2, cudaEventDisableTiming);
        cudaEventCreateWithFlags(&evS4, cudaEventDisableTiming);
        cudaEventCreateWithFlags(&evG3, cudaEventDisableTiming);
        cudaEventCreateWithFlags(&evG2, cudaEventDisableTiming);
        cudaEventCreateWithFlags(&evG1, cudaEventDisableTiming);
        cudaEventCreateWithFlags(&evJ, cudaEventDisableTiming);
        cudaEventCreateWithFlags(&evA, cudaEventDisableTiming);
        cudaEventCreateWithFlags(&evB, cudaEventDisableTiming);
    }

    const dim3 GB(BATCH / 64, 2);    // base passes: 128 blocks
    const dim3 GH(MHALF / 64, 2);    // half-tangent passes: 512 blocks
    cudaStream_t s0 = 0;             // harness/capture stream

    // ---- stream 0: fwd1 (produces S1, H1) ----
    fwd1_kernel<<<BATCH, 128, 0, s0>>>(x, W1, b1, pH1, pS1);
    cudaEventRecord(evS1, s0);

    // ---- tangent halves: T2 = W2 (S1 * t1) — needs only S1 ----
    cudaStreamWaitEvent(s1, evS1, 0);
    gemmT<3, 1, 2><<<GH, 512, 0, s1>>>(nullptr, W2, W1, pS1, nullptr, nullptr, nullptr, nullptr, nullptr, pTa, nullptr, 0);
    cudaStreamWaitEvent(s2, evS1, 0);
    gemmT<3, 1, 2><<<GH, 512, 0, s2>>>(nullptr, W2, W1, pS1, nullptr, nullptr, nullptr, nullptr, nullptr, pTa, nullptr, MHALF);

    // ---- stream 0: base forward chain ----
    gemmT<0, 1, 0><<<GB, 512, 0, s0>>>(pH1, W2, nullptr, nullptr, b2, nullptr, nullptr, nullptr, nullptr, pH2, pS2, 0);
    cudaEventRecord(evS2, s0);
    gemmT<0, 1, 0><<<GB, 512, 0, s0>>>(pH2, W3, nullptr, nullptr, b3, nullptr, nullptr, nullptr, nullptr, pH3, pS3, 0);
    gemmT<0, 1, 6><<<GB, 512, 0, s0>>>(pH3, W4, nullptr, nullptr, b4, nullptr, nullptr, nullptr, nullptr, nullptr, pS4, 0);
    cudaEventRecord(evS4, s0);

    // ---- stream 0: backward chain + J (concurrent with tangent chains) ----
    gemmT<1, 0, 1><<<GB, 512, 0, s0>>>(pS4, W4, W5, nullptr, nullptr, pS3, nullptr, nullptr, nullptr, pG3, pQ3, 0);
    cudaEventRecord(evG3, s0);
    gemmT<0, 0, 1><<<GB, 512, 0, s0>>>(pG3, W3, nullptr, nullptr, nullptr, pS2, nullptr, nullptr, nullptr, pG2, pQ2, 0);
    cudaEventRecord(evG2, s0);
    gemmT<0, 0, 1><<<GB, 512, 0, s0>>>(pG2, W2, nullptr, nullptr, nullptr, pS1, nullptr, nullptr, nullptr, pG1, pQ1, 0);
    cudaEventRecord(evG1, s0);
    proj16_kernel<<<BATCH / 16, 128, 0, s0>>>(pG1, W1, pJ, 0);
    cudaEventRecord(evJ, s0);

    // ---- tangent chain, half A (dirs 0-3) on s1 ----
    cudaStreamWaitEvent(s1, evS2, 0);
    gemmT<2, 1, 2><<<GH, 512, 0, s1>>>(pTa, W3, nullptr, pS2, nullptr, nullptr, nullptr, nullptr, nullptr, pTb, nullptr, 0);
    cudaStreamWaitEvent(s1, evS4, 0);
    gemmT<2, 1, 3><<<GH, 512, 0, s1>>>(pTb, W4, nullptr, pS3, nullptr, pS4, nullptr, nullptr, W5, pTc, nullptr, 0);
    cudaStreamWaitEvent(s1, evG3, 0);
    gemmT<0, 0, 4><<<GH, 512, 0, s1>>>(pTc, W4, nullptr, nullptr, nullptr, pS3, pTb, pQ3, nullptr, pTd, nullptr, 0);
    cudaStreamWaitEvent(s1, evG2, 0);
    gemmT<0, 0, 4><<<GH, 512, 0, s1>>>(pTd, W3, nullptr, nullptr, nullptr, pS2, pTa, pQ2, nullptr, pTc, nullptr, 0);
    cudaStreamWaitEvent(s1, evG1, 0);
    gemmT<0, 0, 5><<<GH, 512, 0, s1>>>(pTc, W2, nullptr, nullptr, nullptr, pS1, nullptr, pQ1, W1, pTb, nullptr, 0);
    proj16_kernel<<<MHALF / 16, 128, 0, s1>>>(pTb, W1, pV, 0);

    // ---- tangent chain, half B (dirs 4-7) on s2 ----
    cudaStreamWaitEvent(s2, evS2, 0);
    gemmT<2, 1, 2><<<GH, 512, 0, s2>>>(pTa, W3, nullptr, pS2, nullptr, nullptr, nullptr, nullptr, nullptr, pTb, nullptr, MHALF);
    cudaStreamWaitEvent(s2, evS4, 0);
    gemmT<2, 1, 3><<<GH, 512, 0, s2>>>(pTb, W4, nullptr, pS3, nullptr, pS4, nullptr, nullptr, W5, pTc, nullptr, MHALF);
    cudaStreamWaitEvent(s2, evG3, 0);
    gemmT<0, 0, 4><<<GH, 512, 0, s2>>>(pTc, W4, nullptr, nullptr, nullptr, pS3, pTb, pQ3, nullptr, pTd, nullptr, MHALF);
    cudaStreamWaitEvent(s2, evG2, 0);
    gemmT<0, 0, 4><<<GH, 512, 0, s2>>>(pTd, W3, nullptr, nullptr, nullptr, pS2, pTa, pQ2, nullptr, pTc, nullptr, MHALF);
    cudaStreamWaitEvent(s2, evG1, 0);
    gemmT<0, 0, 5><<<GH, 512, 0, s2>>>(pTc, W2, nullptr, nullptr, nullptr, pS1, nullptr, pQ1, W1, pTb, nullptr, MHALF);
    proj16_kernel<<<MHALF / 16, 128, 0, s2>>>(pTb, W1, pV, MHALF);
    cudaEventRecord(evB, s2);

    // ---- solve on s1 after both halves + J ----
    cudaStreamWaitEvent(s1, evB, 0);
    cudaStreamWaitEvent(s1, evJ, 0);
    solve_kernel<<<BATCH / 32, 32, 0, s1>>>(pV, pJ, x, out);
    cudaEventRecord(evA, s1);

    // ---- join back onto the capture stream ----
    cudaStreamWaitEvent(s0, evA, 0);
}